// round 10
// baseline (speedup 1.0000x reference)
#include <cuda_runtime.h>
#include <cuda_bf16.h>
#include <cstdint>

#define N1 262144
#define N2 65536
#define N3 16384
#define E1 524288
#define E2 262144
#define HD 256
#define HID 64
#define HEADS 4
#define OUTD 64
#define IND 128
#define NEG_SLOPE 0.2f

// ---------------- device scratch ----------------
__device__ float g_as1[(size_t)N1 * HEADS];
__device__ float g_ad1[(size_t)N2 * HEADS];
__device__ int   g_off1[N2 + 1];
__device__ int   g_cur1[N2];
__device__ int   g_srcs1[E1];
__device__ float g_xagg[(size_t)N2 * HEADS * IND];
__device__ float g_hbn[(size_t)N2 * HD];
__device__ float g_h2[(size_t)N2 * OUTD];
__device__ float g_as2[N2];
__device__ float g_ad2[N3];
__device__ int   g_off2[N3 + 1];
__device__ int   g_cur2[N3];
__device__ int   g_srcs2[E2];
__device__ int   g_bsum[64];

__device__ float g_v1s[IND * HEADS];
__device__ float g_v1d[IND * HEADS];
__device__ float g_v2s[HD];
__device__ float g_v2d[HD];
__device__ float g_bnscale[HD];
__device__ float g_bnshift[HD];

// ---------------- mma.sync helper ----------------
__device__ __forceinline__ void mma16816(float* d, uint32_t a0, uint32_t a1, uint32_t a2,
                                         uint32_t a3, uint32_t b0, uint32_t b1) {
    asm volatile(
        "mma.sync.aligned.m16n8k16.row.col.f32.bf16.bf16.f32 "
        "{%0,%1,%2,%3}, {%4,%5,%6,%7}, {%8,%9}, {%0,%1,%2,%3};"
        : "+f"(d[0]), "+f"(d[1]), "+f"(d[2]), "+f"(d[3])
        : "r"(a0), "r"(a1), "r"(a2), "r"(a3), "r"(b0), "r"(b1));
}

__device__ __forceinline__ void split_bf16(float v, unsigned short& hi, unsigned short& lo) {
    __nv_bfloat16 h = __float2bfloat16_rn(v);
    float r = v - __bfloat162float(h);
    __nv_bfloat16 l = __float2bfloat16_rn(r);
    hi = __bfloat16_as_ushort(h);
    lo = __bfloat16_as_ushort(l);
}
__device__ __forceinline__ uint32_t pack2(unsigned short a, unsigned short b) {
    return (uint32_t)a | ((uint32_t)b << 16);
}

// ---------------- zero scratch ----------------
__global__ void zero_kernel() {
    int i = blockIdx.x * 256 + threadIdx.x;
    if (i < N2) {
        g_cur1[i] = 0;
        g_as2[i] = 0.f;
    }
    if (i < N3) {
        g_cur2[i] = 0;
        g_ad2[i] = 0.f;
    }
}

// ---------------- fold ----------------
__global__ void fold_kernel(const float* __restrict__ W1s, const float* __restrict__ a1s,
                            const float* __restrict__ W1d, const float* __restrict__ a1d,
                            const float* __restrict__ W2s, const float* __restrict__ W2d,
                            const float* __restrict__ a2s, const float* __restrict__ a2d,
                            const float* __restrict__ b1, const float* __restrict__ gamma,
                            const float* __restrict__ beta, const float* __restrict__ mean,
                            const float* __restrict__ var) {
    int t = threadIdx.x;  // 512
    {
        int k = t >> 2, h = t & 3;
        float s1 = 0.f, d1 = 0.f;
        for (int c = 0; c < HID; c++) {
            s1 += W1s[k * HD + h * HID + c] * a1s[h * HID + c];
            d1 += W1d[k * HD + h * HID + c] * a1d[h * HID + c];
        }
        g_v1s[t] = s1;
        g_v1d[t] = d1;
    }
    if (t < HD) {
        float s2 = 0.f, d2 = 0.f;
        for (int c = 0; c < OUTD; c++) {
            s2 += W2s[t * OUTD + c] * a2s[c];
            d2 += W2d[t * OUTD + c] * a2d[c];
        }
        g_v2s[t] = s2;
        g_v2d[t] = d2;
        float sc = gamma[t] * rsqrtf(var[t] + 1e-5f);
        g_bnscale[t] = sc;
        g_bnshift[t] = beta[t] + (b1[t] - mean[t]) * sc;
    }
}

// ---------------- a_src1/a_dst1 ----------------
__global__ __launch_bounds__(256) void asrc1_kernel(const float* __restrict__ x) {
    __shared__ float sv1s[IND * HEADS], sv1d[IND * HEADS];
    int tid = threadIdx.x;
    for (int i = tid; i < IND * HEADS; i += 256) {
        sv1s[i] = g_v1s[i];
        sv1d[i] = g_v1d[i];
    }
    __syncthreads();
    int gw = (blockIdx.x * 256 + tid) >> 5;
    int lane = tid & 31;
    if (gw >= N1) return;
    float4 xv = *(const float4*)(x + (size_t)gw * IND + lane * 4);
    float xr[4] = {xv.x, xv.y, xv.z, xv.w};
    bool need_d = gw < N2;
    float s[4] = {0, 0, 0, 0}, dd[4] = {0, 0, 0, 0};
#pragma unroll
    for (int i = 0; i < 4; i++) {
        int k = lane * 4 + i;
#pragma unroll
        for (int h = 0; h < 4; h++) {
            s[h] += xr[i] * sv1s[k * HEADS + h];
            dd[h] += xr[i] * sv1d[k * HEADS + h];
        }
    }
#pragma unroll
    for (int off = 16; off > 0; off >>= 1)
#pragma unroll
        for (int h = 0; h < 4; h++) {
            s[h] += __shfl_down_sync(0xffffffffu, s[h], off);
            dd[h] += __shfl_down_sync(0xffffffffu, dd[h], off);
        }
    if (lane == 0) {
        *(float4*)(g_as1 + (size_t)gw * HEADS) = make_float4(s[0], s[1], s[2], s[3]);
        if (need_d)
            *(float4*)(g_ad1 + (size_t)gw * HEADS) = make_float4(dd[0], dd[1], dd[2], dd[3]);
    }
}

// ---------------- unified CSR build ----------------
__global__ void deg_all(const int* __restrict__ dst1, const int* __restrict__ dst2) {
    int i = blockIdx.x * 256 + threadIdx.x;
    if (i < E1) atomicAdd(&g_cur1[dst1[i]], 1);
    else atomicAdd(&g_cur2[dst2[i - E1]], 1);
}

__global__ __launch_bounds__(1024) void scan_local_all() {
    __shared__ int sm[1024];
    int b = blockIdx.x, t = threadIdx.x;
    const int* cnt;
    int* off;
    int* bs;
    int lb;
    if (b < 16) { cnt = g_cur1; off = g_off1; bs = g_bsum; lb = b; }
    else        { cnt = g_cur2; off = g_off2; bs = g_bsum + 32; lb = b - 16; }
    int base = lb * 4096 + t * 4;
    int4 v = *(const int4*)(cnt + base);
    int s = v.x + v.y + v.z + v.w;
    sm[t] = s;
    __syncthreads();
    for (int d = 1; d < 1024; d <<= 1) {
        int u = (t >= d) ? sm[t - d] : 0;
        __syncthreads();
        sm[t] += u;
        __syncthreads();
    }
    int excl = sm[t] - s;
    int4 o;
    o.x = excl;
    o.y = excl + v.x;
    o.z = o.y + v.y;
    o.w = o.z + v.z;
    *(int4*)(off + base) = o;
    if (t == 1023) bs[lb] = sm[1023];
}

__global__ void scan_bsum_all() {
    int w = threadIdx.x >> 5, t = threadIdx.x & 31;
    int* bs = g_bsum + w * 32;
    int nb = (w == 0) ? 16 : 4;
    int orig = (t < nb) ? bs[t] : 0;
    int v = orig;
    for (int d = 1; d < 32; d <<= 1) {
        int u = __shfl_up_sync(0xffffffffu, v, d);
        if (t >= d) v += u;
    }
    if (t < nb) bs[t] = v - orig;
    if (t == 31) {
        if (w == 0) g_off1[N2] = v;
        else g_off2[N3] = v;
    }
}

__global__ __launch_bounds__(1024) void scan_add_all() {
    int b = blockIdx.x, t = threadIdx.x;
    if (b < 64) {
        int i = b * 1024 + t;
        int v = g_off1[i] + g_bsum[i >> 12];
        g_off1[i] = v;
        g_cur1[i] = v;
    } else {
        int i = (b - 64) * 1024 + t;
        int v = g_off2[i] + g_bsum[32 + (i >> 12)];
        g_off2[i] = v;
        g_cur2[i] = v;
    }
}

__global__ void fill_all(const int* __restrict__ src1, const int* __restrict__ dst1,
                         const int* __restrict__ src2, const int* __restrict__ dst2) {
    int i = blockIdx.x * 256 + threadIdx.x;
    if (i < E1) {
        int pos = atomicAdd(&g_cur1[dst1[i]], 1);
        g_srcs1[pos] = src1[i];
    } else {
        int j = i - E1;
        int pos = atomicAdd(&g_cur2[dst2[j]], 1);
        g_srcs2[pos] = src2[j];
    }
}

// ---------------- layer1 softmax + aggregation: warp per (dst, 32-ch chunk) ----------------
// 4 warps per dst; alphas recomputed in pass 2 (no alpha array).
__global__ __launch_bounds__(256) void agg1f_kernel(const float* __restrict__ x) {
    int unit = (blockIdx.x * 256 + threadIdx.x) >> 5;
    int lane = threadIdx.x & 31;
    int d = unit >> 2, chunk = unit & 3;
    if (d >= N2) return;
    int beg = g_off1[d], end = g_off1[d + 1];
    float4 adv = *(const float4*)(g_ad1 + (size_t)d * HEADS);
    float ad[4] = {adv.x, adv.y, adv.z, adv.w};
    // pass 1: denominators (lane-parallel over edges)
    float den[4] = {0, 0, 0, 0};
    for (int e = beg + lane; e < end; e += 32) {
        int s = g_srcs1[e];
        float4 asv = *(const float4*)(g_as1 + (size_t)s * HEADS);
        float as[4] = {asv.x, asv.y, asv.z, asv.w};
#pragma unroll
        for (int h = 0; h < 4; h++) {
            float ee = as[h] + ad[h];
            ee = ee > 0.f ? ee : NEG_SLOPE * ee;
            den[h] += expf(ee);
        }
    }
#pragma unroll
    for (int off = 16; off > 0; off >>= 1)
#pragma unroll
        for (int h = 0; h < 4; h++) den[h] += __shfl_xor_sync(0xffffffffu, den[h], off);
    float rd[4];
#pragma unroll
    for (int h = 0; h < 4; h++) rd[h] = 1.f / fmaxf(den[h], 1e-16f);
    // pass 2: aggregate this warp's 32-channel slice
    float acc[4] = {0.f, 0.f, 0.f, 0.f};
    int cbase = chunk * 32 + lane;
    for (int e = beg; e < end; e++) {
        int s = g_srcs1[e];                                      // broadcast
        float4 asv = *(const float4*)(g_as1 + (size_t)s * HEADS); // broadcast sector
        float xv = x[(size_t)s * IND + cbase];
        float as[4] = {asv.x, asv.y, asv.z, asv.w};
#pragma unroll
        for (int h = 0; h < 4; h++) {
            float ee = as[h] + ad[h];
            ee = ee > 0.f ? ee : NEG_SLOPE * ee;
            acc[h] += (expf(ee) * rd[h]) * xv;
        }
    }
#pragma unroll
    for (int h = 0; h < 4; h++)
        g_xagg[((size_t)d * HEADS + h) * IND + cbase] = acc[h];
}

// ---------------- GEMM-L1 (mma.sync) + BN/ELU + a2 folds in epilogue ----------------
#define SA 132
#define AH_OFF 0
#define AL_OFF (128 * SA)
#define BH_OFF (2 * 128 * SA)
#define BL_OFF (2 * 128 * SA + 64 * SA)
#define BF16_ELEMS (2 * 128 * SA + 2 * 64 * SA)
#define L1_SMEM (BF16_ELEMS * 2 + 256 * 4)
__global__ __launch_bounds__(256) void gemm_l1_mma(const float* __restrict__ W1s) {
    extern __shared__ __nv_bfloat16 smb[];
    unsigned short* sm = (unsigned short*)smb;
    float* cons = (float*)(sm + BF16_ELEMS);  // sc[64] sh[64] v2s[64] v2d[64]
    int tid = threadIdx.x;
    int h = blockIdx.y;
    int row0 = blockIdx.x * 128;

    if (tid < 64) {
        int col = h * HID + tid;
        cons[tid]       = g_bnscale[col];
        cons[64 + tid]  = g_bnshift[col];
        cons[128 + tid] = g_v2s[col];
        cons[192 + tid] = g_v2d[col];
    }
    for (int i = tid; i < 128 * 32; i += 256) {
        int row = i >> 5, k = (i & 31) * 4;
        float4 v = *(const float4*)(g_xagg + ((size_t)(row0 + row) * HEADS + h) * IND + k);
        unsigned short hi[4], lo[4];
        split_bf16(v.x, hi[0], lo[0]);
        split_bf16(v.y, hi[1], lo[1]);
        split_bf16(v.z, hi[2], lo[2]);
        split_bf16(v.w, hi[3], lo[3]);
        int o = row * SA + k;
        *(uint2*)(sm + AH_OFF + o) = make_uint2(pack2(hi[0], hi[1]), pack2(hi[2], hi[3]));
        *(uint2*)(sm + AL_OFF + o) = make_uint2(pack2(lo[0], lo[1]), pack2(lo[2], lo[3]));
    }
    for (int i = tid; i < 64 * 128; i += 256) {
        int n = i & 63, k = i >> 6;
        float v = W1s[k * HD + h * HID + n];
        unsigned short hi, lo;
        split_bf16(v, hi, lo);
        sm[BH_OFF + n * SA + k] = hi;
        sm[BL_OFF + n * SA + k] = lo;
    }
    __syncthreads();

    int wid = tid >> 5, lane = tid & 31;
    int gr = lane >> 2, tg = lane & 3;
    int r0 = wid * 16;
    float acc[8][4];
#pragma unroll
    for (int nt = 0; nt < 8; nt++)
#pragma unroll
        for (int j = 0; j < 4; j++) acc[nt][j] = 0.f;

#pragma unroll
    for (int ks = 0; ks < 8; ks++) {
        int k0 = ks * 16;
        int abase = (r0 + gr) * SA + k0 + tg * 2;
        uint32_t ah0 = *(const uint32_t*)(sm + AH_OFF + abase);
        uint32_t ah1 = *(const uint32_t*)(sm + AH_OFF + abase + 8 * SA);
        uint32_t ah2 = *(const uint32_t*)(sm + AH_OFF + abase + 8);
        uint32_t ah3 = *(const uint32_t*)(sm + AH_OFF + abase + 8 * SA + 8);
        uint32_t al0 = *(const uint32_t*)(sm + AL_OFF + abase);
        uint32_t al1 = *(const uint32_t*)(sm + AL_OFF + abase + 8 * SA);
        uint32_t al2 = *(const uint32_t*)(sm + AL_OFF + abase + 8);
        uint32_t al3 = *(const uint32_t*)(sm + AL_OFF + abase + 8 * SA + 8);
#pragma unroll
        for (int nt = 0; nt < 8; nt++) {
            int bbase = (nt * 8 + gr) * SA + k0 + tg * 2;
            uint32_t bh0 = *(const uint32_t*)(sm + BH_OFF + bbase);
            uint32_t bh1 = *(const uint32_t*)(sm + BH_OFF + bbase + 8);
            uint32_t bl0 = *(const uint32_t*)(sm + BL_OFF + bbase);
            uint32_t bl1 = *(const uint32_t*)(sm + BL_OFF + bbase + 8);
            mma16816(acc[nt], ah0, ah1, ah2, ah3, bh0, bh1);
            mma16816(acc[nt], ah0, ah1, ah2, ah3, bl0, bl1);
            mma16816(acc[nt], al0, al1, al2, al3, bh0, bh1);
        }
    }

    int r1 = row0 + r0 + gr;
    int r2 = r1 + 8;
    float ps1 = 0.f, pd1 = 0.f, ps2 = 0.f, pd2 = 0.f;
#pragma unroll
    for (int nt = 0; nt < 8; nt++) {
        int n = nt * 8 + tg * 2;
        float sc0 = cons[n], sc1 = cons[n + 1], sh0 = cons[64 + n], sh1 = cons[64 + n + 1];
        float vs0 = cons[128 + n], vs1 = cons[128 + n + 1];
        float vd0 = cons[192 + n], vd1 = cons[192 + n + 1];
        float v0 = acc[nt][0] * sc0 + sh0;
        float v1 = acc[nt][1] * sc1 + sh1;
        float v2 = acc[nt][2] * sc0 + sh0;
        float v3 = acc[nt][3] * sc1 + sh1;
        v0 = v0 > 0.f ? v0 : expm1f(v0);
        v1 = v1 > 0.f ? v1 : expm1f(v1);
        v2 = v2 > 0.f ? v2 : expm1f(v2);
        v3 = v3 > 0.f ? v3 : expm1f(v3);
        *(float2*)(g_hbn + (size_t)r1 * HD + h * HID + n) = make_float2(v0, v1);
        *(float2*)(g_hbn + (size_t)r2 * HD + h * HID + n) = make_float2(v2, v3);
        ps1 += v0 * vs0 + v1 * vs1;
        ps2 += v2 * vs0 + v3 * vs1;
        pd1 += v0 * vd0 + v1 * vd1;
        pd2 += v2 * vd0 + v3 * vd1;
    }
#pragma unroll
    for (int off = 2; off > 0; off >>= 1) {
        ps1 += __shfl_down_sync(0xffffffffu, ps1, off, 4);
        ps2 += __shfl_down_sync(0xffffffffu, ps2, off, 4);
        pd1 += __shfl_down_sync(0xffffffffu, pd1, off, 4);
        pd2 += __shfl_down_sync(0xffffffffu, pd2, off, 4);
    }
    if (tg == 0) {
        atomicAdd(&g_as2[r1], ps1);
        atomicAdd(&g_as2[r2], ps2);
        if (r1 < N3) atomicAdd(&g_ad2[r1], pd1);
        if (r2 < N3) atomicAdd(&g_ad2[r2], pd2);
    }
}

// ---------------- GEMM-L2 (mma.sync): h2 = hbn @ W2s ----------------
#define L2_SMEM (BF16_ELEMS * 2)
__global__ __launch_bounds__(256) void gemm_l2_mma(const float* __restrict__ W2s) {
    extern __shared__ __nv_bfloat16 smb[];
    unsigned short* sm = (unsigned short*)smb;
    int tid = threadIdx.x;
    int row0 = blockIdx.x * 128;
    int wid = tid >> 5, lane = tid & 31;
    int gr = lane >> 2, tg = lane & 3;
    int r0 = wid * 16;
    float acc[8][4];
#pragma unroll
    for (int nt = 0; nt < 8; nt++)
#pragma unroll
        for (int j = 0; j < 4; j++) acc[nt][j] = 0.f;

    for (int kb = 0; kb < HD; kb += 128) {
        if (kb) __syncthreads();
        for (int i = tid; i < 128 * 32; i += 256) {
            int row = i >> 5, k = (i & 31) * 4;
            float4 v = *(const float4*)(g_hbn + (size_t)(row0 + row) * HD + kb + k);
            unsigned short hi[4], lo[4];
            split_bf16(v.x, hi[0], lo[0]);
            split_bf16(v.y, hi[1], lo[1]);
            split_bf16(v.z, hi[2], lo[2]);
            split_bf16(v.w, hi[3], lo[3]);
            int o = row * SA + k;
            *(uint2*)(sm + AH_OFF + o) = make_uint2(pack2(hi[0], hi[1]), pack2(hi[2], hi[3]));
            *(uint2*)(sm + AL_OFF + o) = make_uint2(pack2(lo[0], lo[1]), pack2(lo[2], lo[3]));
        }
        for (int i = tid; i < 64 * 128; i += 256) {
            int n = i & 63, k = i >> 6;
            float v = W2s[(kb + k) * OUTD + n];
            unsigned short hi, lo;
            split_bf16(v, hi, lo);
            sm[BH_OFF + n * SA + k] = hi;
            sm[BL_OFF + n * SA + k] = lo;
        }
        __syncthreads();

#pragma unroll
        for (int ks = 0; ks < 8; ks++) {
            int k0 = ks * 16;
            int abase = (r0 + gr) * SA + k0 + tg * 2;
            uint32_t ah0 = *(const uint32_t*)(sm + AH_OFF + abase);
            uint32_t ah1 = *(const uint32_t*)(sm + AH_OFF + abase + 8 * SA);
            uint32_t ah2 = *(const uint32_t*)(sm + AH_OFF + abase + 8);
            uint32_t ah3 = *(const uint32_t*)(sm + AH_OFF + abase + 8 * SA + 8);
            uint32_t al0 = *(const uint32_t*)(sm + AL_OFF + abase);
            uint32_t al1 = *(const uint32_t*)(sm + AL_OFF + abase + 8 * SA);
            uint32_t al2 = *(const uint32_t*)(sm + AL_OFF + abase + 8);
            uint32_t al3 = *(const uint32_t*)(sm + AL_OFF + abase + 8 * SA + 8);
#pragma unroll
            for (int nt = 0; nt < 8; nt++) {
                int bbase = (nt * 8 + gr) * SA + k0 + tg * 2;
                uint32_t bh0 = *(const uint32_t*)(sm + BH_OFF + bbase);
                uint32_t bh1 = *(const uint32_t*)(sm + BH_OFF + bbase + 8);
                uint32_t bl0 = *(const uint32_t*)(sm + BL_OFF + bbase);
                uint32_t bl1 = *(const uint32_t*)(sm + BL_OFF + bbase + 8);
                mma16816(acc[nt], ah0, ah1, ah2, ah3, bh0, bh1);
                mma16816(acc[nt], ah0, ah1, ah2, ah3, bl0, bl1);
                mma16816(acc[nt], al0, al1, al2, al3, bh0, bh1);
            }
        }
    }

    int r1 = row0 + r0 + gr;
    int r2 = r1 + 8;
#pragma unroll
    for (int nt = 0; nt < 8; nt++) {
        int n = nt * 8 + tg * 2;
        *(float2*)(g_h2 + (size_t)r1 * OUTD + n) = make_float2(acc[nt][0], acc[nt][1]);
        *(float2*)(g_h2 + (size_t)r2 * OUTD + n) = make_float2(acc[nt][2], acc[nt][3]);
    }
}

// ---------------- layer2 softmax + aggregation: warp per (dst, 32-ch chunk) ----------------
__global__ __launch_bounds__(256) void agg2f_kernel(float* __restrict__ out,
                                                    const float* __restrict__ b2) {
    int unit = (blockIdx.x * 256 + threadIdx.x) >> 5;
    int lane = threadIdx.x & 31;
    int d = unit >> 1, chunk = unit & 1;
    if (d >= N3) return;
    int beg = g_off2[d], end = g_off2[d + 1];
    float ad = g_ad2[d];
    float den = 0.f;
    for (int e = beg + lane; e < end; e += 32) {
        int s = g_srcs2[e];
        float ee = g_as2[s] + ad;
        ee = ee > 0.f ? ee : NEG_SLOPE * ee;
        den += expf(ee);
    }
#pragma unroll
    for (int off = 16; off > 0; off >>= 1) den += __shfl_xor_sync(0xffffffffu, den, off);
    float rd = 1.f / fmaxf(den, 1e-16f);
    float acc = 0.f;
    int cbase = chunk * 32 + lane;
    for (int e = beg; e < end; e++) {
        int s = g_srcs2[e];                 // broadcast
        float ee = g_as2[s] + ad;           // broadcast
        ee = ee > 0.f ? ee : NEG_SLOPE * ee;
        float a = expf(ee) * rd;
        acc += a * g_h2[(size_t)s * OUTD + cbase];
    }
    out[(size_t)d * OUTD + cbase] = acc + b2[cbase];
}

// ---------------- launch ----------------
extern "C" void kernel_launch(void* const* d_in, const int* in_sizes, int n_in,
                              void* d_out, int out_size) {
    const float* x        = (const float*)d_in[0];
    const float* W1_src   = (const float*)d_in[1];
    const float* W1_dst   = (const float*)d_in[2];
    const float* att1_src = (const float*)d_in[3];
    const float* att1_dst = (const float*)d_in[4];
    const float* b1       = (const float*)d_in[5];
    const float* gamma    = (const float*)d_in[6];
    const float* beta     = (const float*)d_in[7];
    const float* run_mean = (const float*)d_in[8];
    const float* run_var  = (const float*)d_in[9];
    const float* W2_src   = (const float*)d_in[10];
    const float* W2_dst   = (const float*)d_in[11];
    const float* att2_src = (const float*)d_in[12];
    const float* att2_dst = (const float*)d_in[13];
    const float* b2       = (const float*)d_in[14];
    const int*   src1     = (const int*)d_in[15];
    const int*   dst1     = (const int*)d_in[16];
    const int*   src2     = (const int*)d_in[17];
    const int*   dst2     = (const int*)d_in[18];
    float* out = (float*)d_out;

    cudaFuncSetAttribute(gemm_l1_mma, cudaFuncAttributeMaxDynamicSharedMemorySize, L1_SMEM);
    cudaFuncSetAttribute(gemm_l2_mma, cudaFuncAttributeMaxDynamicSharedMemorySize, L2_SMEM);

    zero_kernel<<<N2 / 256, 256>>>();
    fold_kernel<<<1, 512>>>(W1_src, att1_src, W1_dst, att1_dst, W2_src, W2_dst,
                            att2_src, att2_dst, b1, gamma, beta, run_mean, run_var);

    asrc1_kernel<<<N1 * 32 / 256, 256>>>(x);

    deg_all<<<(E1 + E2) / 256, 256>>>(dst1, dst2);
    scan_local_all<<<20, 1024>>>();
    scan_bsum_all<<<1, 64>>>();
    scan_add_all<<<80, 1024>>>();
    fill_all<<<(E1 + E2) / 256, 256>>>(src1, dst1, src2, dst2);

    agg1f_kernel<<<N2 * HEADS * 32 / 256, 256>>>(x);

    gemm_l1_mma<<<dim3(N2 / 128, HEADS), 256, L1_SMEM>>>(W1_src);

    gemm_l2_mma<<<N2 / 128, 256, L2_SMEM>>>(W2_src);

    agg2f_kernel<<<N3 * 2 * 32 / 256, 256>>>(out, b2);
}

// round 11
// speedup vs baseline: 1.3025x; 1.3025x over previous
#include <cuda_runtime.h>
#include <cuda_bf16.h>
#include <cstdint>

#define N1 262144
#define N2 65536
#define N3 16384
#define E1 524288
#define E2 262144
#define HD 256
#define HID 64
#define HEADS 4
#define OUTD 64
#define IND 128
#define NEG_SLOPE 0.2f

// ---------------- device scratch ----------------
__device__ float g_as1[(size_t)N1 * HEADS];
__device__ float g_ad1[(size_t)N2 * HEADS];
__device__ int   g_off1[N2 + 1];
__device__ int   g_cur1[N2];
__device__ int   g_srcs1[E1];
__device__ float g_xagg[(size_t)N2 * HEADS * IND];
__device__ float g_hbn[(size_t)N2 * HD];
__device__ float g_h2[(size_t)N2 * OUTD];
__device__ float g_as2[N2];
__device__ float g_ad2[N3];
__device__ int   g_off2[N3 + 1];
__device__ int   g_cur2[N3];
__device__ int   g_srcs2[E2];
__device__ int   g_bsum[64];

__device__ float g_v1s[IND * HEADS];
__device__ float g_v1d[IND * HEADS];
__device__ float g_v2s[HD];
__device__ float g_v2d[HD];
__device__ float g_bnscale[HD];
__device__ float g_bnshift[HD];

// ---------------- mma.sync helper ----------------
__device__ __forceinline__ void mma16816(float* d, uint32_t a0, uint32_t a1, uint32_t a2,
                                         uint32_t a3, uint32_t b0, uint32_t b1) {
    asm volatile(
        "mma.sync.aligned.m16n8k16.row.col.f32.bf16.bf16.f32 "
        "{%0,%1,%2,%3}, {%4,%5,%6,%7}, {%8,%9}, {%0,%1,%2,%3};"
        : "+f"(d[0]), "+f"(d[1]), "+f"(d[2]), "+f"(d[3])
        : "r"(a0), "r"(a1), "r"(a2), "r"(a3), "r"(b0), "r"(b1));
}

__device__ __forceinline__ void split_bf16(float v, unsigned short& hi, unsigned short& lo) {
    __nv_bfloat16 h = __float2bfloat16_rn(v);
    float r = v - __bfloat162float(h);
    __nv_bfloat16 l = __float2bfloat16_rn(r);
    hi = __bfloat16_as_ushort(h);
    lo = __bfloat16_as_ushort(l);
}
__device__ __forceinline__ uint32_t pack2(unsigned short a, unsigned short b) {
    return (uint32_t)a | ((uint32_t)b << 16);
}

// ---------------- zero scratch ----------------
__global__ void zero_kernel() {
    int i = blockIdx.x * 256 + threadIdx.x;
    if (i < N2) {
        g_cur1[i] = 0;
        g_as2[i] = 0.f;
    }
    if (i < N3) {
        g_cur2[i] = 0;
        g_ad2[i] = 0.f;
    }
}

// ---------------- fold (parallel: warp per output) ----------------
__global__ __launch_bounds__(256) void fold_kernel(
    const float* __restrict__ W1s, const float* __restrict__ a1s,
    const float* __restrict__ W1d, const float* __restrict__ a1d,
    const float* __restrict__ W2s, const float* __restrict__ W2d,
    const float* __restrict__ a2s, const float* __restrict__ a2d,
    const float* __restrict__ b1, const float* __restrict__ gamma,
    const float* __restrict__ beta, const float* __restrict__ mean,
    const float* __restrict__ var) {
    int w = (blockIdx.x * 256 + threadIdx.x) >> 5;
    int lane = threadIdx.x & 31;
    if (w < 512) {
        int k = w >> 2, h = w & 3;
        const float* w1sp = W1s + k * HD + h * HID;
        const float* w1dp = W1d + k * HD + h * HID;
        const float* a1sp = a1s + h * HID;
        const float* a1dp = a1d + h * HID;
        float s1 = w1sp[lane] * a1sp[lane] + w1sp[lane + 32] * a1sp[lane + 32];
        float d1 = w1dp[lane] * a1dp[lane] + w1dp[lane + 32] * a1dp[lane + 32];
#pragma unroll
        for (int off = 16; off > 0; off >>= 1) {
            s1 += __shfl_down_sync(0xffffffffu, s1, off);
            d1 += __shfl_down_sync(0xffffffffu, d1, off);
        }
        if (lane == 0) {
            g_v1s[w] = s1;
            g_v1d[w] = d1;
        }
    } else if (w < 768) {
        int t = w - 512;
        float s2 = W2s[t * OUTD + lane] * a2s[lane] + W2s[t * OUTD + lane + 32] * a2s[lane + 32];
        float d2 = W2d[t * OUTD + lane] * a2d[lane] + W2d[t * OUTD + lane + 32] * a2d[lane + 32];
#pragma unroll
        for (int off = 16; off > 0; off >>= 1) {
            s2 += __shfl_down_sync(0xffffffffu, s2, off);
            d2 += __shfl_down_sync(0xffffffffu, d2, off);
        }
        if (lane == 0) {
            g_v2s[t] = s2;
            g_v2d[t] = d2;
            float sc = gamma[t] * rsqrtf(var[t] + 1e-5f);
            g_bnscale[t] = sc;
            g_bnshift[t] = beta[t] + (b1[t] - mean[t]) * sc;
        }
    }
}

// ---------------- a_src1/a_dst1 ----------------
__global__ __launch_bounds__(256) void asrc1_kernel(const float* __restrict__ x) {
    __shared__ float sv1s[IND * HEADS], sv1d[IND * HEADS];
    int tid = threadIdx.x;
    for (int i = tid; i < IND * HEADS; i += 256) {
        sv1s[i] = g_v1s[i];
        sv1d[i] = g_v1d[i];
    }
    __syncthreads();
    int gw = (blockIdx.x * 256 + tid) >> 5;
    int lane = tid & 31;
    if (gw >= N1) return;
    float4 xv = *(const float4*)(x + (size_t)gw * IND + lane * 4);
    float xr[4] = {xv.x, xv.y, xv.z, xv.w};
    bool need_d = gw < N2;
    float s[4] = {0, 0, 0, 0}, dd[4] = {0, 0, 0, 0};
#pragma unroll
    for (int i = 0; i < 4; i++) {
        int k = lane * 4 + i;
#pragma unroll
        for (int h = 0; h < 4; h++) {
            s[h] += xr[i] * sv1s[k * HEADS + h];
            dd[h] += xr[i] * sv1d[k * HEADS + h];
        }
    }
#pragma unroll
    for (int off = 16; off > 0; off >>= 1)
#pragma unroll
        for (int h = 0; h < 4; h++) {
            s[h] += __shfl_down_sync(0xffffffffu, s[h], off);
            dd[h] += __shfl_down_sync(0xffffffffu, dd[h], off);
        }
    if (lane == 0) {
        *(float4*)(g_as1 + (size_t)gw * HEADS) = make_float4(s[0], s[1], s[2], s[3]);
        if (need_d)
            *(float4*)(g_ad1 + (size_t)gw * HEADS) = make_float4(dd[0], dd[1], dd[2], dd[3]);
    }
}

// ---------------- unified CSR build ----------------
__global__ void deg_all(const int* __restrict__ dst1, const int* __restrict__ dst2) {
    int i = blockIdx.x * 256 + threadIdx.x;
    if (i < E1) atomicAdd(&g_cur1[dst1[i]], 1);
    else atomicAdd(&g_cur2[dst2[i - E1]], 1);
}

__global__ __launch_bounds__(1024) void scan_local_all() {
    __shared__ int sm[1024];
    int b = blockIdx.x, t = threadIdx.x;
    const int* cnt;
    int* off;
    int* bs;
    int lb;
    if (b < 16) { cnt = g_cur1; off = g_off1; bs = g_bsum; lb = b; }
    else        { cnt = g_cur2; off = g_off2; bs = g_bsum + 32; lb = b - 16; }
    int base = lb * 4096 + t * 4;
    int4 v = *(const int4*)(cnt + base);
    int s = v.x + v.y + v.z + v.w;
    sm[t] = s;
    __syncthreads();
    for (int d = 1; d < 1024; d <<= 1) {
        int u = (t >= d) ? sm[t - d] : 0;
        __syncthreads();
        sm[t] += u;
        __syncthreads();
    }
    int excl = sm[t] - s;
    int4 o;
    o.x = excl;
    o.y = excl + v.x;
    o.z = o.y + v.y;
    o.w = o.z + v.z;
    *(int4*)(off + base) = o;
    if (t == 1023) bs[lb] = sm[1023];
}

__global__ void scan_bsum_all() {
    int w = threadIdx.x >> 5, t = threadIdx.x & 31;
    int* bs = g_bsum + w * 32;
    int nb = (w == 0) ? 16 : 4;
    int orig = (t < nb) ? bs[t] : 0;
    int v = orig;
    for (int d = 1; d < 32; d <<= 1) {
        int u = __shfl_up_sync(0xffffffffu, v, d);
        if (t >= d) v += u;
    }
    if (t < nb) bs[t] = v - orig;
    if (t == 31) {
        if (w == 0) g_off1[N2] = v;
        else g_off2[N3] = v;
    }
}

__global__ __launch_bounds__(1024) void scan_add_all() {
    int b = blockIdx.x, t = threadIdx.x;
    if (b < 64) {
        int i = b * 1024 + t;
        int v = g_off1[i] + g_bsum[i >> 12];
        g_off1[i] = v;
        g_cur1[i] = v;
    } else {
        int i = (b - 64) * 1024 + t;
        int v = g_off2[i] + g_bsum[32 + (i >> 12)];
        g_off2[i] = v;
        g_cur2[i] = v;
    }
}

__global__ void fill_all(const int* __restrict__ src1, const int* __restrict__ dst1,
                         const int* __restrict__ src2, const int* __restrict__ dst2) {
    int i = blockIdx.x * 256 + threadIdx.x;
    if (i < E1) {
        int pos = atomicAdd(&g_cur1[dst1[i]], 1);
        g_srcs1[pos] = src1[i];
    } else {
        int j = i - E1;
        int pos = atomicAdd(&g_cur2[dst2[j]], 1);
        g_srcs2[pos] = src2[j];
    }
}

// ---------------- layer1 softmax + aggregation: warp per dst, lane-resident edges ----------------
__global__ __launch_bounds__(256) void agg1f_kernel(const float* __restrict__ x) {
    int d = (blockIdx.x * 256 + threadIdx.x) >> 5;
    int lane = threadIdx.x & 31;
    if (d >= N2) return;
    int beg = g_off1[d], end = g_off1[d + 1];
    int deg = end - beg;
    float4 adv = *(const float4*)(g_ad1 + (size_t)d * HEADS);
    float ad[4] = {adv.x, adv.y, adv.z, adv.w};
    // lane-resident first 32 edges: src index + exp-logit per head
    int e0 = beg + lane;
    bool val = e0 < end;
    int s_l = val ? g_srcs1[e0] : 0;
    float p_l[4] = {0.f, 0.f, 0.f, 0.f};
    float den[4] = {0.f, 0.f, 0.f, 0.f};
    if (val) {
        float4 asv = *(const float4*)(g_as1 + (size_t)s_l * HEADS);
        float as[4] = {asv.x, asv.y, asv.z, asv.w};
#pragma unroll
        for (int h = 0; h < 4; h++) {
            float ee = as[h] + ad[h];
            ee = ee > 0.f ? ee : NEG_SLOPE * ee;
            p_l[h] = expf(ee);
            den[h] = p_l[h];
        }
    }
    // rare tail (> 32 edges): denominators only
    for (int e = beg + 32 + lane; e < end; e += 32) {
        int s = g_srcs1[e];
        float4 asv = *(const float4*)(g_as1 + (size_t)s * HEADS);
        float as[4] = {asv.x, asv.y, asv.z, asv.w};
#pragma unroll
        for (int h = 0; h < 4; h++) {
            float ee = as[h] + ad[h];
            ee = ee > 0.f ? ee : NEG_SLOPE * ee;
            den[h] += expf(ee);
        }
    }
#pragma unroll
    for (int off = 16; off > 0; off >>= 1)
#pragma unroll
        for (int h = 0; h < 4; h++) den[h] += __shfl_xor_sync(0xffffffffu, den[h], off);
    float rd[4];
#pragma unroll
    for (int h = 0; h < 4; h++) rd[h] = 1.f / fmaxf(den[h], 1e-16f);

    float acc[4][4];
#pragma unroll
    for (int h = 0; h < 4; h++)
#pragma unroll
        for (int j = 0; j < 4; j++) acc[h][j] = 0.f;
    int nfast = deg < 32 ? deg : 32;
#pragma unroll 4
    for (int i = 0; i < nfast; i++) {
        int s = __shfl_sync(0xffffffffu, s_l, i);
        float a0 = __shfl_sync(0xffffffffu, p_l[0], i) * rd[0];
        float a1 = __shfl_sync(0xffffffffu, p_l[1], i) * rd[1];
        float a2 = __shfl_sync(0xffffffffu, p_l[2], i) * rd[2];
        float a3 = __shfl_sync(0xffffffffu, p_l[3], i) * rd[3];
        float4 xv = *(const float4*)(x + (size_t)s * IND + lane * 4);
        float xr[4] = {xv.x, xv.y, xv.z, xv.w};
#pragma unroll
        for (int j = 0; j < 4; j++) {
            acc[0][j] += a0 * xr[j];
            acc[1][j] += a1 * xr[j];
            acc[2][j] += a2 * xr[j];
            acc[3][j] += a3 * xr[j];
        }
    }
    // rare slow tail: whole warp per edge
    for (int e = beg + 32; e < end; e++) {
        int s = g_srcs1[e];
        float4 asv = *(const float4*)(g_as1 + (size_t)s * HEADS);
        float as[4] = {asv.x, asv.y, asv.z, asv.w};
        float a[4];
#pragma unroll
        for (int h = 0; h < 4; h++) {
            float ee = as[h] + ad[h];
            ee = ee > 0.f ? ee : NEG_SLOPE * ee;
            a[h] = expf(ee) * rd[h];
        }
        float4 xv = *(const float4*)(x + (size_t)s * IND + lane * 4);
        float xr[4] = {xv.x, xv.y, xv.z, xv.w};
#pragma unroll
        for (int h = 0; h < 4; h++)
#pragma unroll
            for (int j = 0; j < 4; j++) acc[h][j] += a[h] * xr[j];
    }
#pragma unroll
    for (int h = 0; h < 4; h++)
        *(float4*)(g_xagg + ((size_t)d * HEADS + h) * IND + lane * 4) =
            make_float4(acc[h][0], acc[h][1], acc[h][2], acc[h][3]);
}

// ---------------- GEMM-L1 (mma.sync) + BN/ELU + a2 folds in epilogue ----------------
#define SA 132
#define AH_OFF 0
#define AL_OFF (128 * SA)
#define BH_OFF (2 * 128 * SA)
#define BL_OFF (2 * 128 * SA + 64 * SA)
#define BF16_ELEMS (2 * 128 * SA + 2 * 64 * SA)
#define L1_SMEM (BF16_ELEMS * 2 + 256 * 4)
__global__ __launch_bounds__(256) void gemm_l1_mma(const float* __restrict__ W1s) {
    extern __shared__ __nv_bfloat16 smb[];
    unsigned short* sm = (unsigned short*)smb;
    float* cons = (float*)(sm + BF16_ELEMS);  // sc[64] sh[64] v2s[64] v2d[64]
    int tid = threadIdx.x;
    int h = blockIdx.y;
    int row0 = blockIdx.x * 128;

    if (tid < 64) {
        int col = h * HID + tid;
        cons[tid]       = g_bnscale[col];
        cons[64 + tid]  = g_bnshift[col];
        cons[128 + tid] = g_v2s[col];
        cons[192 + tid] = g_v2d[col];
    }
    for (int i = tid; i < 128 * 32; i += 256) {
        int row = i >> 5, k = (i & 31) * 4;
        float4 v = *(const float4*)(g_xagg + ((size_t)(row0 + row) * HEADS + h) * IND + k);
        unsigned short hi[4], lo[4];
        split_bf16(v.x, hi[0], lo[0]);
        split_bf16(v.y, hi[1], lo[1]);
        split_bf16(v.z, hi[2], lo[2]);
        split_bf16(v.w, hi[3], lo[3]);
        int o = row * SA + k;
        *(uint2*)(sm + AH_OFF + o) = make_uint2(pack2(hi[0], hi[1]), pack2(hi[2], hi[3]));
        *(uint2*)(sm + AL_OFF + o) = make_uint2(pack2(lo[0], lo[1]), pack2(lo[2], lo[3]));
    }
    for (int i = tid; i < 64 * 128; i += 256) {
        int n = i & 63, k = i >> 6;
        float v = W1s[k * HD + h * HID + n];
        unsigned short hi, lo;
        split_bf16(v, hi, lo);
        sm[BH_OFF + n * SA + k] = hi;
        sm[BL_OFF + n * SA + k] = lo;
    }
    __syncthreads();

    int wid = tid >> 5, lane = tid & 31;
    int gr = lane >> 2, tg = lane & 3;
    int r0 = wid * 16;
    float acc[8][4];
#pragma unroll
    for (int nt = 0; nt < 8; nt++)
#pragma unroll
        for (int j = 0; j < 4; j++) acc[nt][j] = 0.f;

#pragma unroll
    for (int ks = 0; ks < 8; ks++) {
        int k0 = ks * 16;
        int abase = (r0 + gr) * SA + k0 + tg * 2;
        uint32_t ah0 = *(const uint32_t*)(sm + AH_OFF + abase);
        uint32_t ah1 = *(const uint32_t*)(sm + AH_OFF + abase + 8 * SA);
        uint32_t ah2 = *(const uint32_t*)(sm + AH_OFF + abase + 8);
        uint32_t ah3 = *(const uint32_t*)(sm + AH_OFF + abase + 8 * SA + 8);
        uint32_t al0 = *(const uint32_t*)(sm + AL_OFF + abase);
        uint32_t al1 = *(const uint32_t*)(sm + AL_OFF + abase + 8 * SA);
        uint32_t al2 = *(const uint32_t*)(sm + AL_OFF + abase + 8);
        uint32_t al3 = *(const uint32_t*)(sm + AL_OFF + abase + 8 * SA + 8);
#pragma unroll
        for (int nt = 0; nt < 8; nt++) {
            int bbase = (nt * 8 + gr) * SA + k0 + tg * 2;
            uint32_t bh0 = *(const uint32_t*)(sm + BH_OFF + bbase);
            uint32_t bh1 = *(const uint32_t*)(sm + BH_OFF + bbase + 8);
            uint32_t bl0 = *(const uint32_t*)(sm + BL_OFF + bbase);
            uint32_t bl1 = *(const uint32_t*)(sm + BL_OFF + bbase + 8);
            mma16816(acc[nt], ah0, ah1, ah2, ah3, bh0, bh1);
            mma16816(acc[nt], ah0, ah1, ah2, ah3, bl0, bl1);
            mma16816(acc[nt], al0, al1, al2, al3, bh0, bh1);
        }
    }

    int r1 = row0 + r0 + gr;
    int r2 = r1 + 8;
    float ps1 = 0.f, pd1 = 0.f, ps2 = 0.f, pd2 = 0.f;
#pragma unroll
    for (int nt = 0; nt < 8; nt++) {
        int n = nt * 8 + tg * 2;
        float sc0 = cons[n], sc1 = cons[n + 1], sh0 = cons[64 + n], sh1 = cons[64 + n + 1];
        float vs0 = cons[128 + n], vs1 = cons[128 + n + 1];
        float vd0 = cons[192 + n], vd1 = cons[192 + n + 1];
        float v0 = acc[nt][0] * sc0 + sh0;
        float v1 = acc[nt][1] * sc1 + sh1;
        float v2 = acc[nt][2] * sc0 + sh0;
        float v3 = acc[nt][3] * sc1 + sh1;
        v0 = v0 > 0.f ? v0 : expm1f(v0);
        v1 = v1 > 0.f ? v1 : expm1f(v1);
        v2 = v2 > 0.f ? v2 : expm1f(v2);
        v3 = v3 > 0.f ? v3 : expm1f(v3);
        *(float2*)(g_hbn + (size_t)r1 * HD + h * HID + n) = make_float2(v0, v1);
        *(float2*)(g_hbn + (size_t)r2 * HD + h * HID + n) = make_float2(v2, v3);
        ps1 += v0 * vs0 + v1 * vs1;
        ps2 += v2 * vs0 + v3 * vs1;
        pd1 += v0 * vd0 + v1 * vd1;
        pd2 += v2 * vd0 + v3 * vd1;
    }
#pragma unroll
    for (int off = 2; off > 0; off >>= 1) {
        ps1 += __shfl_down_sync(0xffffffffu, ps1, off, 4);
        ps2 += __shfl_down_sync(0xffffffffu, ps2, off, 4);
        pd1 += __shfl_down_sync(0xffffffffu, pd1, off, 4);
        pd2 += __shfl_down_sync(0xffffffffu, pd2, off, 4);
    }
    if (tg == 0) {
        atomicAdd(&g_as2[r1], ps1);
        atomicAdd(&g_as2[r2], ps2);
        if (r1 < N3) atomicAdd(&g_ad2[r1], pd1);
        if (r2 < N3) atomicAdd(&g_ad2[r2], pd2);
    }
}

// ---------------- GEMM-L2 (mma.sync): h2 = hbn @ W2s ----------------
#define L2_SMEM (BF16_ELEMS * 2)
__global__ __launch_bounds__(256) void gemm_l2_mma(const float* __restrict__ W2s) {
    extern __shared__ __nv_bfloat16 smb[];
    unsigned short* sm = (unsigned short*)smb;
    int tid = threadIdx.x;
    int row0 = blockIdx.x * 128;
    int wid = tid >> 5, lane = tid & 31;
    int gr = lane >> 2, tg = lane & 3;
    int r0 = wid * 16;
    float acc[8][4];
#pragma unroll
    for (int nt = 0; nt < 8; nt++)
#pragma unroll
        for (int j = 0; j < 4; j++) acc[nt][j] = 0.f;

    for (int kb = 0; kb < HD; kb += 128) {
        if (kb) __syncthreads();
        for (int i = tid; i < 128 * 32; i += 256) {
            int row = i >> 5, k = (i & 31) * 4;
            float4 v = *(const float4*)(g_hbn + (size_t)(row0 + row) * HD + kb + k);
            unsigned short hi[4], lo[4];
            split_bf16(v.x, hi[0], lo[0]);
            split_bf16(v.y, hi[1], lo[1]);
            split_bf16(v.z, hi[2], lo[2]);
            split_bf16(v.w, hi[3], lo[3]);
            int o = row * SA + k;
            *(uint2*)(sm + AH_OFF + o) = make_uint2(pack2(hi[0], hi[1]), pack2(hi[2], hi[3]));
            *(uint2*)(sm + AL_OFF + o) = make_uint2(pack2(lo[0], lo[1]), pack2(lo[2], lo[3]));
        }
        for (int i = tid; i < 64 * 128; i += 256) {
            int n = i & 63, k = i >> 6;
            float v = W2s[(kb + k) * OUTD + n];
            unsigned short hi, lo;
            split_bf16(v, hi, lo);
            sm[BH_OFF + n * SA + k] = hi;
            sm[BL_OFF + n * SA + k] = lo;
        }
        __syncthreads();

#pragma unroll
        for (int ks = 0; ks < 8; ks++) {
            int k0 = ks * 16;
            int abase = (r0 + gr) * SA + k0 + tg * 2;
            uint32_t ah0 = *(const uint32_t*)(sm + AH_OFF + abase);
            uint32_t ah1 = *(const uint32_t*)(sm + AH_OFF + abase + 8 * SA);
            uint32_t ah2 = *(const uint32_t*)(sm + AH_OFF + abase + 8);
            uint32_t ah3 = *(const uint32_t*)(sm + AH_OFF + abase + 8 * SA + 8);
            uint32_t al0 = *(const uint32_t*)(sm + AL_OFF + abase);
            uint32_t al1 = *(const uint32_t*)(sm + AL_OFF + abase + 8 * SA);
            uint32_t al2 = *(const uint32_t*)(sm + AL_OFF + abase + 8);
            uint32_t al3 = *(const uint32_t*)(sm + AL_OFF + abase + 8 * SA + 8);
#pragma unroll
            for (int nt = 0; nt < 8; nt++) {
                int bbase = (nt * 8 + gr) * SA + k0 + tg * 2;
                uint32_t bh0 = *(const uint32_t*)(sm + BH_OFF + bbase);
                uint32_t bh1 = *(const uint32_t*)(sm + BH_OFF + bbase + 8);
                uint32_t bl0 = *(const uint32_t*)(sm + BL_OFF + bbase);
                uint32_t bl1 = *(const uint32_t*)(sm + BL_OFF + bbase + 8);
                mma16816(acc[nt], ah0, ah1, ah2, ah3, bh0, bh1);
                mma16816(acc[nt], ah0, ah1, ah2, ah3, bl0, bl1);
                mma16816(acc[nt], al0, al1, al2, al3, bh0, bh1);
            }
        }
    }

    int r1 = row0 + r0 + gr;
    int r2 = r1 + 8;
#pragma unroll
    for (int nt = 0; nt < 8; nt++) {
        int n = nt * 8 + tg * 2;
        *(float2*)(g_h2 + (size_t)r1 * OUTD + n) = make_float2(acc[nt][0], acc[nt][1]);
        *(float2*)(g_h2 + (size_t)r2 * OUTD + n) = make_float2(acc[nt][2], acc[nt][3]);
    }
}

// ---------------- layer2 softmax + aggregation: warp per dst, lane-resident edges ----------------
__global__ __launch_bounds__(256) void agg2f_kernel(float* __restrict__ out,
                                                    const float* __restrict__ b2) {
    int d = (blockIdx.x * 256 + threadIdx.x) >> 5;
    int lane = threadIdx.x & 31;
    if (d >= N3) return;
    int beg = g_off2[d], end = g_off2[d + 1];
    int deg = end - beg;
    float ad = g_ad2[d];
    int e0 = beg + lane;
    bool val = e0 < end;
    int s_l = val ? g_srcs2[e0] : 0;
    float p_l = 0.f, den = 0.f;
    if (val) {
        float ee = g_as2[s_l] + ad;
        ee = ee > 0.f ? ee : NEG_SLOPE * ee;
        p_l = expf(ee);
        den = p_l;
    }
    for (int e = beg + 32 + lane; e < end; e += 32) {
        int s = g_srcs2[e];
        float ee = g_as2[s] + ad;
        ee = ee > 0.f ? ee : NEG_SLOPE * ee;
        den += expf(ee);
    }
#pragma unroll
    for (int off = 16; off > 0; off >>= 1) den += __shfl_xor_sync(0xffffffffu, den, off);
    float rd = 1.f / fmaxf(den, 1e-16f);
    float ax = 0.f, ay = 0.f;
    int nfast = deg < 32 ? deg : 32;
#pragma unroll 4
    for (int i = 0; i < nfast; i++) {
        int s = __shfl_sync(0xffffffffu, s_l, i);
        float a = __shfl_sync(0xffffffffu, p_l, i) * rd;
        float2 v = *(const float2*)(g_h2 + (size_t)s * OUTD + lane * 2);
        ax += a * v.x;
        ay += a * v.y;
    }
    for (int e = beg + 32; e < end; e++) {
        int s = g_srcs2[e];
        float ee = g_as2[s] + ad;
        ee = ee > 0.f ? ee : NEG_SLOPE * ee;
        float a = expf(ee) * rd;
        float2 v = *(const float2*)(g_h2 + (size_t)s * OUTD + lane * 2);
        ax += a * v.x;
        ay += a * v.y;
    }
    out[(size_t)d * OUTD + lane * 2]     = ax + b2[lane * 2];
    out[(size_t)d * OUTD + lane * 2 + 1] = ay + b2[lane * 2 + 1];
}

// ---------------- launch ----------------
extern "C" void kernel_launch(void* const* d_in, const int* in_sizes, int n_in,
                              void* d_out, int out_size) {
    const float* x        = (const float*)d_in[0];
    const float* W1_src   = (const float*)d_in[1];
    const float* W1_dst   = (const float*)d_in[2];
    const float* att1_src = (const float*)d_in[3];
    const float* att1_dst = (const float*)d_in[4];
    const float* b1       = (const float*)d_in[5];
    const float* gamma    = (const float*)d_in[6];
    const float* beta     = (const float*)d_in[7];
    const float* run_mean = (const float*)d_in[8];
    const float* run_var  = (const float*)d_in[9];
    const float* W2_src   = (const float*)d_in[10];
    const float* W2_dst   = (const float*)d_in[11];
    const float* att2_src = (const float*)d_in[12];
    const float* att2_dst = (const float*)d_in[13];
    const float* b2       = (const float*)d_in[14];
    const int*   src1     = (const int*)d_in[15];
    const int*   dst1     = (const int*)d_in[16];
    const int*   src2     = (const int*)d_in[17];
    const int*   dst2     = (const int*)d_in[18];
    float* out = (float*)d_out;

    cudaFuncSetAttribute(gemm_l1_mma, cudaFuncAttributeMaxDynamicSharedMemorySize, L1_SMEM);
    cudaFuncSetAttribute(gemm_l2_mma, cudaFuncAttributeMaxDynamicSharedMemorySize, L2_SMEM);

    zero_kernel<<<N2 / 256, 256>>>();
    fold_kernel<<<96, 256>>>(W1_src, att1_src, W1_dst, att1_dst, W2_src, W2_dst,
                             att2_src, att2_dst, b1, gamma, beta, run_mean, run_var);

    asrc1_kernel<<<N1 * 32 / 256, 256>>>(x);

    deg_all<<<(E1 + E2) / 256, 256>>>(dst1, dst2);
    scan_local_all<<<20, 1024>>>();
    scan_bsum_all<<<1, 64>>>();
    scan_add_all<<<80, 1024>>>();
    fill_all<<<(E1 + E2) / 256, 256>>>(src1, dst1, src2, dst2);

    agg1f_kernel<<<N2 * 32 / 256, 256>>>(x);

    gemm_l1_mma<<<dim3(N2 / 128, HEADS), 256, L1_SMEM>>>(W1_src);

    gemm_l2_mma<<<N2 / 128, 256, L2_SMEM>>>(W2_src);

    agg2f_kernel<<<N3 * 32 / 256, 256>>>(out, b2);
}